// round 16
// baseline (speedup 1.0000x reference)
#include <cuda_runtime.h>
#include <cuda_bf16.h>
#include <cuda_fp16.h>
#include <math.h>
#include <stdint.h>

#define S_TOT 3900
#define SP    3904        // padded seq (61*64)
#define DIM   1536
#define NH    12
#define HD    128
#define CC    64
#define NTILES 61         // SP/64
#define NSPLIT 3          // flash KV splits

// ---------------- scratch ----------------
__device__ float g_q [S_TOT * DIM];   // q fp32 -> flash partial 0 -> O-proj partial 0
__device__ float g_k [S_TOT * DIM];   // k fp32 -> flash partial 1 -> O-proj partial 1
__device__ float g_o2[S_TOT * DIM];   // flash partial 2 -> O-proj partial 2
__device__ float g_stat[NSPLIT * NH * 2 * 4096];

__device__ __half g_x16 [S_TOT * DIM];    // x fp16
__device__ __half g_q16 [S_TOT * DIM];    // Q fp16 (post rmsnorm+rope)
__device__ __half g_k16 [S_TOT * DIM];    // K fp16
__device__ __half g_ao16[S_TOT * DIM];    // attention out fp16
__device__ __half g_vt16[DIM * SP];       // V transposed fp16

__device__ __half g_w16q[DIM * DIM];
__device__ __half g_w16k[DIM * DIM];
__device__ __half g_w16v[DIM * DIM];
__device__ __half g_w16o[DIM * DIM];

// ================= helpers =================
__device__ __forceinline__ uint32_t smem_u32(const void* p) {
    uint32_t a;
    asm("{ .reg .u64 t; cvta.to.shared.u64 t, %1; cvt.u32.u64 %0, t; }" : "=r"(a) : "l"(p));
    return a;
}
__device__ __forceinline__ void ldsm4(uint32_t& r0, uint32_t& r1, uint32_t& r2, uint32_t& r3,
                                      uint32_t addr) {
    asm volatile("ldmatrix.sync.aligned.m8n8.x4.shared.b16 {%0,%1,%2,%3}, [%4];"
                 : "=r"(r0), "=r"(r1), "=r"(r2), "=r"(r3) : "r"(addr));
}
__device__ __forceinline__ void mma16816h(float* c, const uint32_t* a, const uint32_t* b) {
    asm volatile(
        "mma.sync.aligned.m16n8k16.row.col.f32.f16.f16.f32 "
        "{%0,%1,%2,%3}, {%4,%5,%6,%7}, {%8,%9}, {%0,%1,%2,%3};"
        : "+f"(c[0]), "+f"(c[1]), "+f"(c[2]), "+f"(c[3])
        : "r"(a[0]), "r"(a[1]), "r"(a[2]), "r"(a[3]), "r"(b[0]), "r"(b[1]));
}
#define CP16(dst, src, sz) \
    asm volatile("cp.async.cg.shared.global [%0], [%1], 16, %2;" \
        :: "r"(dst), "l"(src), "r"(sz) : "memory")
#define CP_COMMIT() asm volatile("cp.async.commit_group;" ::: "memory")
#define CP_WAIT0()  asm volatile("cp.async.wait_group 0;" ::: "memory")
#define CP_WAIT1()  asm volatile("cp.async.wait_group 1;" ::: "memory")

__device__ __forceinline__ uint32_t pack_h2(float x, float y) {
    __half2 t = __floats2half2_rn(x, y);
    return *(uint32_t*)&t;
}
#define STATIDX(sp, hh, ml, s) ((((sp) * NH + (hh)) * 2 + (ml)) * 4096 + (s))

// ================= prep kernels =================
__global__ __launch_bounds__(256)
void convert_x_kernel(const float* __restrict__ x, __half* __restrict__ x16) {
    int i = blockIdx.x * 256 + threadIdx.x;
    const int tot4 = S_TOT * DIM / 4;
    if (i >= tot4) return;
    float4 v = ((const float4*)x)[i];
    ((uint2*)x16)[i] = make_uint2(pack_h2(v.x, v.y), pack_h2(v.z, v.w));
}

// W[K][N] fp32 -> Wt[N][K] fp16 ; 4 weights in one launch (blockIdx.z)
struct WPtrs { const float* w[4]; __half* t16[4]; };

__global__ __launch_bounds__(256)
void transw_kernel(WPtrs p) {
    __shared__ float t[32][33];
    const float* W = p.w[blockIdx.z];
    __half* T = p.t16[blockIdx.z];
    const int n0 = blockIdx.x * 32, k0 = blockIdx.y * 32;
    const int tx = threadIdx.x, ty = threadIdx.y;
    #pragma unroll
    for (int i = 0; i < 4; i++)
        t[ty + i * 8][tx] = W[(size_t)(k0 + ty + i * 8) * DIM + n0 + tx];
    __syncthreads();
    #pragma unroll
    for (int i = 0; i < 4; i++) {
        float v = t[tx][ty + i * 8];
        T[(size_t)(n0 + ty + i * 8) * DIM + k0 + tx] = __float2half_rn(v);
    }
}

// RMSNorm + RoPE -> fp16 (y==0 Q, y==1 K)
__global__ __launch_bounds__(256)
void rmsnorm_rope_conv(const float* __restrict__ tq, const float* __restrict__ gq,
                       __half* __restrict__ qo16,
                       const float* __restrict__ tk, const float* __restrict__ gk,
                       __half* __restrict__ ko16,
                       const float* __restrict__ freqs, const int* __restrict__ grid_sizes) {
    const int s = blockIdx.x;
    const int tid = threadIdx.x;
    const int isq = (blockIdx.y == 0);
    const float* t  = isq ? tq : tk;
    const float* g  = isq ? gq : gk;
    __half* o16 = isq ? qo16 : ko16;
    const float* row = t + (size_t)s * DIM;

    float ss = 0.f;
    for (int i = tid; i < DIM / 4; i += 256) {
        float4 v = ((const float4*)row)[i];
        ss += v.x * v.x + v.y * v.y + v.z * v.z + v.w * v.w;
    }
    #pragma unroll
    for (int off = 16; off; off >>= 1) ss += __shfl_xor_sync(0xffffffffu, ss, off);
    __shared__ float red[8];
    if ((tid & 31) == 0) red[tid >> 5] = ss;
    __syncthreads();
    if (tid == 0) {
        float tot = 0.f;
        #pragma unroll
        for (int i = 0; i < 8; i++) tot += red[i];
        red[0] = tot;
    }
    __syncthreads();
    const float inv = rsqrtf(red[0] * (1.f / DIM) + 1e-6f);

    const int H = grid_sizes[1], W = grid_sizes[2];
    const int fi = s / (H * W);
    const int rem = s % (H * W);
    const int hi = rem / W;
    const int wi = rem % W;
    const int c3 = CC / 3, c0 = CC - 2 * c3;

    for (int p = tid; p < NH * CC; p += 256) {
        int j = p % CC;
        int head = p / CC;
        int idx = head * HD + 2 * j;
        float a = row[idx]     * inv * g[idx];
        float b = row[idx + 1] * inv * g[idx + 1];
        int pos = (j < c0) ? fi : ((j < c0 + c3) ? hi : wi);
        float cs = freqs[(pos * CC + j) * 2 + 0];
        float sn = freqs[(pos * CC + j) * 2 + 1];
        float ra = a * cs - b * sn;
        float rb = a * sn + b * cs;
        *(uint32_t*)(o16 + (size_t)s * DIM + idx) = pack_h2(ra, rb);
    }
}

// ================= HMMA GEMM: fp16 x fp16, single pass, 3-stage cp.async =========
#define G_ST   40
#define G_BUFB 10240
#define G_AS   0               // 3 bufs: 0..30720
#define G_BS   30720           // 3 bufs: 30720..61440
#define G_SMEM 61440           // V staging (34816) fits inside
#define VT_ST  136

struct QKVArgs {
    const __half* b16[3];
    const float* bias[3];
    float* c[3];
    __half* vt16;              // if non-null: mat==2 writes transposed fp16
};

__global__ __launch_bounds__(256)
void gemm_mma(const __half* __restrict__ A, QKVArgs args, int M, int splitk) {
    extern __shared__ char smc[];
    const uint32_t sb = smem_u32(smc);
    const int tid = threadIdx.x;
    const int lane = tid & 31;
    const int wid = tid >> 5;
    const int wm = wid & 1;
    const int wn = wid >> 1;
    int mat = blockIdx.x / 12;
    const int n0 = (blockIdx.x % 12) * 128;
    const int m0 = blockIdx.y * 128;
    int kt0 = 0, ktn = 48;
    if (splitk) { kt0 = blockIdx.z * 16; ktn = 16; mat = blockIdx.z; }
    const __half* B = args.b16[splitk ? 0 : mat];
    const float* bias = args.bias[mat];
    float* C = args.c[mat];

    float c[4][4][4];
    #pragma unroll
    for (int i = 0; i < 4; i++)
        #pragma unroll
        for (int j = 0; j < 4; j++)
            #pragma unroll
            for (int q = 0; q < 4; q++) c[i][j][q] = 0.f;

    auto stage = [&](int kt, int buf) {
        const int k0 = kt * 32;
        #pragma unroll
        for (int cix = 0; cix < 2; cix++) {
            int ch = tid + cix * 256;           // 0..511
            int row = ch >> 2, cc = (ch & 3) * 8;
            uint32_t so = (uint32_t)(row * G_ST + cc) * 2 + (uint32_t)buf * G_BUFB;
            int szA = (m0 + row < M) ? 16 : 0;
            const __half* pa = A + (size_t)(m0 + row) * DIM + k0 + cc;
            const __half* pb = B + (size_t)(n0 + row) * DIM + k0 + cc;
            CP16(sb + G_AS + so, pa, szA);
            CP16(sb + G_BS + so, pb, 16);
        }
        CP_COMMIT();
    };

    stage(kt0, 0);
    stage(kt0 + 1, 1);

    const int a_row = (lane & 15);
    const int a_col = ((lane >> 1) & 8);
    const int b_row = (lane & 7) + ((lane & 16) >> 1);
    const int b_col = (lane & 8);

    for (int kti = 0; kti < ktn; kti++) {
        CP_WAIT1();                      // stage kti complete (kti+1 may be in flight)
        __syncthreads();
        if (kti < ktn - 2) stage(kt0 + kti + 2, (kti + 2) % 3);
        const int bo = (kti % 3) * G_BUFB;
        #pragma unroll
        for (int kc = 0; kc < 32; kc += 16) {
            uint32_t af[4][4], bf[4][2];
            #pragma unroll
            for (int mt = 0; mt < 4; mt++)
                ldsm4(af[mt][0], af[mt][1], af[mt][2], af[mt][3],
                      sb + G_AS + bo + (uint32_t)((wm * 64 + mt * 16 + a_row) * G_ST + kc + a_col) * 2);
            #pragma unroll
            for (int np = 0; np < 2; np++) {
                uint32_t r0, r1, r2, r3;
                ldsm4(r0, r1, r2, r3,
                      sb + G_BS + bo + (uint32_t)((wn * 32 + np * 16 + b_row) * G_ST + kc + b_col) * 2);
                bf[np*2][0] = r0; bf[np*2][1] = r1; bf[np*2+1][0] = r2; bf[np*2+1][1] = r3;
            }
            #pragma unroll
            for (int mt = 0; mt < 4; mt++)
                #pragma unroll
                for (int nt = 0; nt < 4; nt++)
                    mma16816h(c[mt][nt], af[mt], bf[nt]);
        }
        __syncthreads();
    }
    CP_WAIT0();                          // drain the tail in-flight group

    if (args.vt16 != nullptr && mat == 2) {
        // ---- V epilogue: transposed fp16 via smem staging ----
        unsigned short* TH = (unsigned short*)smc;
        #pragma unroll
        for (int mt = 0; mt < 4; mt++) {
            #pragma unroll
            for (int nt = 0; nt < 4; nt++) {
                int row0 = wm * 64 + mt * 16 + (lane >> 2);
                int coll = wn * 32 + nt * 8 + (lane & 3) * 2;
                float b0 = bias[n0 + coll], b1 = bias[n0 + coll + 1];
                TH[coll * VT_ST + row0] =
                    __half_as_ushort(__float2half_rn(c[mt][nt][0] + b0));
                TH[(coll + 1) * VT_ST + row0] =
                    __half_as_ushort(__float2half_rn(c[mt][nt][1] + b1));
                TH[coll * VT_ST + row0 + 8] =
                    __half_as_ushort(__float2half_rn(c[mt][nt][2] + b0));
                TH[(coll + 1) * VT_ST + row0 + 8] =
                    __half_as_ushort(__float2half_rn(c[mt][nt][3] + b1));
            }
        }
        __syncthreads();
        #pragma unroll
        for (int it = 0; it < 8; it++) {
            int ch = tid + it * 256;         // 0..2047
            int drow = ch >> 4;
            int c8 = (ch & 15) * 8;
            if (m0 + c8 + 8 <= SP) {         // guard: last M-block overhangs SP
                uint4 v = *(uint4*)(smc + (uint32_t)(drow * VT_ST + c8) * 2);
                *(uint4*)(args.vt16 + (size_t)(n0 + drow) * SP + m0 + c8) = v;
            }
        }
    } else {
        #pragma unroll
        for (int mt = 0; mt < 4; mt++) {
            #pragma unroll
            for (int nt = 0; nt < 4; nt++) {
                int row = m0 + wm * 64 + mt * 16 + (lane >> 2);
                int col = n0 + wn * 32 + nt * 8 + (lane & 3) * 2;
                float b0 = 0.f, b1 = 0.f;
                if (!splitk) { b0 = bias[col]; b1 = bias[col + 1]; }
                if (row < M)
                    *(float2*)&C[(size_t)row * DIM + col] =
                        make_float2(c[mt][nt][0] + b0, c[mt][nt][1] + b1);
                if (row + 8 < M)
                    *(float2*)&C[(size_t)(row + 8) * DIM + col] =
                        make_float2(c[mt][nt][2] + b0, c[mt][nt][3] + b1);
            }
        }
    }
}

// ================= add split-K partials + bias (3-way) =================
__global__ __launch_bounds__(256)
void addbias_kernel(const float* __restrict__ p0, const float* __restrict__ p1,
                    const float* __restrict__ p2, const float* __restrict__ bias,
                    float* __restrict__ out) {
    int i = blockIdx.x * 256 + threadIdx.x;
    const int tot4 = S_TOT * DIM / 4;
    if (i >= tot4) return;
    float4 a = ((const float4*)p0)[i];
    float4 b = ((const float4*)p1)[i];
    float4 d = ((const float4*)p2)[i];
    float4 bb = ((const float4*)bias)[i % (DIM / 4)];
    ((float4*)out)[i] = make_float4(a.x + b.x + d.x + bb.x, a.y + b.y + d.y + bb.y,
                                    a.z + b.z + d.z + bb.z, a.w + b.w + d.w + bb.w);
}

// ================= HMMA flash attention: fp16, 3-buffer KV pipeline =================
#define F_QST 136
#define F_VST 72
#define F_Q    0               // Q fp16: 128*136*2 = 34816
#define F_STG  34816
#define F_STGB 35840           // K 17408 | V 18432
#define F_SMEM (F_STG + 3 * F_STGB)   // 142336

__global__ __launch_bounds__(256)
void flash_mma(const __half* __restrict__ Q16, const __half* __restrict__ K16,
               const __half* __restrict__ V16,
               float* __restrict__ O0, float* __restrict__ O1, float* __restrict__ O2,
               float* __restrict__ stat, const int* __restrict__ seq_lens) {
    extern __shared__ char smc[];
    const uint32_t sb = smem_u32(smc);
    const int tid = threadIdx.x;
    const int lane = tid & 31;
    const int wid = tid >> 5;
    const int r0w = wid * 16;
    const int h = blockIdx.y;
    const int q0 = blockIdx.x * 128;
    const int sp = blockIdx.z;                      // 0,1,2
    const int t_begin = (sp == 0) ? 0 : 21 + (sp - 1) * 20;
    const int t_cnt   = (sp == 0) ? 21 : 20;
    const int seqlen = seq_lens[0];
    const float scale2 = 0.08838834764831845f * 1.4426950408889634f;  // /sqrt(128)*log2(e)

    // ---- Q tile [128 x 128] fp16 via cp.async (own group) ----
    #pragma unroll
    for (int cix = 0; cix < 8; cix++) {
        int ch = tid + cix * 256;                   // 0..2047
        int row = ch >> 4, cc = (ch & 15) * 8;
        int sz = (q0 + row < S_TOT) ? 16 : 0;
        const __half* gq = Q16 + (size_t)(q0 + row) * DIM + h * HD + cc;
        CP16(sb + F_Q + (uint32_t)(row * F_QST + cc) * 2, gq, sz);
    }
    CP_COMMIT();

    auto kv_stage = [&](int gt, int buf) {
        const int k0 = gt * 64;
        const uint32_t base = sb + F_STG + (uint32_t)buf * F_STGB;
        #pragma unroll
        for (int cix = 0; cix < 4; cix++) {
            int ch = tid + cix * 256;            // 0..1023
            {
                int row = ch >> 4, cc = (ch & 15) * 8;
                int sz = (k0 + row < S_TOT) ? 16 : 0;
                const __half* gk = K16 + (size_t)(k0 + row) * DIM + h * HD + cc;
                CP16(base + (uint32_t)(row * F_QST + cc) * 2, gk, sz);
            }
            {
                int row = ch >> 3, cc = (ch & 7) * 8;
                const __half* gv = V16 + (size_t)(h * HD + row) * SP + k0 + cc;
                CP16(base + 17408 + (uint32_t)(row * F_VST + cc) * 2, gv, 16);
            }
        }
        CP_COMMIT();
    };

    kv_stage(t_begin, 0);
    kv_stage(t_begin + 1, 1);            // t_cnt >= 20 always

    float m0s = -1e30f, m1s = -1e30f, l0s = 0.f, l1s = 0.f;
    float o[16][4];
    #pragma unroll
    for (int i = 0; i < 16; i++)
        #pragma unroll
        for (int j = 0; j < 4; j++) o[i][j] = 0.f;

    const int a_row = (lane & 15);
    const int a_col = ((lane >> 1) & 8);
    const int b_row = (lane & 7) + ((lane & 16) >> 1);
    const int b_col = (lane & 8);

    for (int lt = 0; lt < t_cnt; lt++) {
        const int gt = t_begin + lt;
        const int k0 = gt * 64;
        CP_WAIT1();                      // stage lt ready; stage lt+1 may be in flight
        __syncthreads();
        if (lt + 2 < t_cnt) kv_stage(gt + 2, (lt + 2) % 3);

        const uint32_t kb = sb + F_STG + (uint32_t)(lt % 3) * F_STGB;
        const uint32_t vb = kb + 17408;

        // ---- S = Q K^T (fp16, 1 pass) ----
        float c[8][4];
        #pragma unroll
        for (int nt = 0; nt < 8; nt++)
            #pragma unroll
            for (int j = 0; j < 4; j++) c[nt][j] = 0.f;

        #pragma unroll
        for (int kc8 = 0; kc8 < 8; kc8++) {
            const int kc = kc8 * 16;
            uint32_t aq[4], bk[8][2];
            ldsm4(aq[0], aq[1], aq[2], aq[3],
                  sb + F_Q + (uint32_t)((r0w + a_row) * F_QST + kc + a_col) * 2);
            #pragma unroll
            for (int np = 0; np < 4; np++) {
                uint32_t r0, r1, r2, r3;
                ldsm4(r0, r1, r2, r3,
                      kb + (uint32_t)((np * 16 + b_row) * F_QST + kc + b_col) * 2);
                bk[np*2][0] = r0; bk[np*2][1] = r1; bk[np*2+1][0] = r2; bk[np*2+1][1] = r3;
            }
            #pragma unroll
            for (int nt = 0; nt < 8; nt++)
                mma16816h(c[nt], aq, bk[nt]);
        }

        // ---- scale (log2 domain) + mask ----
        #pragma unroll
        for (int nt = 0; nt < 8; nt++) {
            int colb = k0 + nt * 8 + (lane & 3) * 2;
            #pragma unroll
            for (int j = 0; j < 4; j++) {
                float v = c[nt][j] * scale2;
                c[nt][j] = (colb + (j & 1) < seqlen) ? v : -1e30f;
            }
        }

        // ---- online softmax (exp2) ----
        float mx0 = -1e30f, mx1 = -1e30f;
        #pragma unroll
        for (int nt = 0; nt < 8; nt++) {
            mx0 = fmaxf(mx0, fmaxf(c[nt][0], c[nt][1]));
            mx1 = fmaxf(mx1, fmaxf(c[nt][2], c[nt][3]));
        }
        mx0 = fmaxf(mx0, __shfl_xor_sync(0xffffffffu, mx0, 1));
        mx0 = fmaxf(mx0, __shfl_xor_sync(0xffffffffu, mx0, 2));
        mx1 = fmaxf(mx1, __shfl_xor_sync(0xffffffffu, mx1, 1));
        mx1 = fmaxf(mx1, __shfl_xor_sync(0xffffffffu, mx1, 2));
        float mn0 = fmaxf(m0s, mx0), mn1 = fmaxf(m1s, mx1);
        float al0 = exp2f(m0s - mn0), al1 = exp2f(m1s - mn1);
        m0s = mn0; m1s = mn1;
        float ls0 = 0.f, ls1 = 0.f;
        #pragma unroll
        for (int nt = 0; nt < 8; nt++) {
            c[nt][0] = exp2f(c[nt][0] - mn0); ls0 += c[nt][0];
            c[nt][1] = exp2f(c[nt][1] - mn0); ls0 += c[nt][1];
            c[nt][2] = exp2f(c[nt][2] - mn1); ls1 += c[nt][2];
            c[nt][3] = exp2f(c[nt][3] - mn1); ls1 += c[nt][3];
        }
        ls0 += __shfl_xor_sync(0xffffffffu, ls0, 1);
        ls0 += __shfl_xor_sync(0xffffffffu, ls0, 2);
        ls1 += __shfl_xor_sync(0xffffffffu, ls1, 1);
        ls1 += __shfl_xor_sync(0xffffffffu, ls1, 2);
        l0s = l0s * al0 + ls0;
        l1s = l1s * al1 + ls1;

        // ---- pack P into fp16 A fragments ----
        uint32_t ph[4][4];
        #pragma unroll
        for (int kc2 = 0; kc2 < 4; kc2++) {
            ph[kc2][0] = pack_h2(c[2*kc2][0],   c[2*kc2][1]);
            ph[kc2][1] = pack_h2(c[2*kc2][2],   c[2*kc2][3]);
            ph[kc2][2] = pack_h2(c[2*kc2+1][0], c[2*kc2+1][1]);
            ph[kc2][3] = pack_h2(c[2*kc2+1][2], c[2*kc2+1][3]);
        }

        // ---- rescale O ----
        #pragma unroll
        for (int nt = 0; nt < 16; nt++) {
            o[nt][0] *= al0; o[nt][1] *= al0;
            o[nt][2] *= al1; o[nt][3] *= al1;
        }

        // ---- O += P V (fp16, 1 pass) ----
        #pragma unroll
        for (int kc2 = 0; kc2 < 4; kc2++) {
            #pragma unroll
            for (int np = 0; np < 8; np++) {
                uint32_t v0, v1, v2, v3;
                ldsm4(v0, v1, v2, v3,
                      vb + (uint32_t)((np * 16 + b_row) * F_VST + kc2 * 16 + b_col) * 2);
                uint32_t b0[2] = {v0, v1}, b1[2] = {v2, v3};
                mma16816h(o[2*np],   ph[kc2], b0);
                mma16816h(o[2*np+1], ph[kc2], b1);
            }
        }
    }

    // ---- write UNNORMALIZED partial + stats ----
    float* Op = (sp == 0) ? O0 : ((sp == 1) ? O1 : O2);
    const int rA = q0 + r0w + (lane >> 2);
    const int rB = rA + 8;
    #pragma unroll
    for (int nt = 0; nt < 16; nt++) {
        int col = h * HD + nt * 8 + (lane & 3) * 2;
        if (rA < S_TOT)
            *(float2*)&Op[(size_t)rA * DIM + col] = make_float2(o[nt][0], o[nt][1]);
        if (rB < S_TOT)
            *(float2*)&Op[(size_t)rB * DIM + col] = make_float2(o[nt][2], o[nt][3]);
    }
    if ((lane & 3) == 0) {
        if (rA < S_TOT) {
            stat[STATIDX(sp, h, 0, rA)] = m0s;
            stat[STATIDX(sp, h, 1, rA)] = l0s;
        }
        if (rB < S_TOT) {
            stat[STATIDX(sp, h, 0, rB)] = m1s;
            stat[STATIDX(sp, h, 1, rB)] = l1s;
        }
    }
    CP_WAIT0();   // drain any in-flight tail stage before CTA exit
}

// ================= combine split-KV partials (3-way) -> fp16 =================
__global__ __launch_bounds__(128)
void combine_kernel(const float* __restrict__ O0, const float* __restrict__ O1,
                    const float* __restrict__ O2, const float* __restrict__ stat,
                    __half* __restrict__ AO16) {
    const int s = blockIdx.x;
    const int h = blockIdx.y;
    const int c = threadIdx.x;
    float mA = stat[STATIDX(0, h, 0, s)], lA = stat[STATIDX(0, h, 1, s)];
    float mB = stat[STATIDX(1, h, 0, s)], lB = stat[STATIDX(1, h, 1, s)];
    float mC = stat[STATIDX(2, h, 0, s)], lC = stat[STATIDX(2, h, 1, s)];
    float m = fmaxf(fmaxf(mA, mB), mC);
    float aA = exp2f(mA - m), aB = exp2f(mB - m), aC = exp2f(mC - m);
    float inv = 1.f / (lA * aA + lB * aB + lC * aC);
    size_t idx = (size_t)s * DIM + h * HD + c;
    float o = (O0[idx] * aA + O1[idx] * aB + O2[idx] * aC) * inv;
    AO16[idx] = __float2half_rn(o);
}

// ---------------- launch ----------------
extern "C" void kernel_launch(void* const* d_in, const int* in_sizes, int n_in,
                              void* d_out, int out_size) {
    const float* x        = (const float*)d_in[0];
    const int*   seq_lens = (const int*)  d_in[1];
    const int*   grid_sz  = (const int*)  d_in[2];
    const float* freqs    = (const float*)d_in[3];
    const float* Wq       = (const float*)d_in[4];
    const float* bq       = (const float*)d_in[5];
    const float* Wk       = (const float*)d_in[6];
    const float* bk       = (const float*)d_in[7];
    const float* Wv       = (const float*)d_in[8];
    const float* bv       = (const float*)d_in[9];
    const float* Wo       = (const float*)d_in[10];
    const float* bo       = (const float*)d_in[11];
    const float* gq       = (const float*)d_in[12];
    const float* gk       = (const float*)d_in[13];
    float* out = (float*)d_out;

    float *q, *k, *o2, *stat;
    __half *x16, *q16, *k16, *ao16, *vt16;
    __half *w16q, *w16k, *w16v, *w16o;
    cudaGetSymbolAddress((void**)&q, g_q);
    cudaGetSymbolAddress((void**)&k, g_k);
    cudaGetSymbolAddress((void**)&o2, g_o2);
    cudaGetSymbolAddress((void**)&stat, g_stat);
    cudaGetSymbolAddress((void**)&x16, g_x16);
    cudaGetSymbolAddress((void**)&q16, g_q16);
    cudaGetSymbolAddress((void**)&k16, g_k16);
    cudaGetSymbolAddress((void**)&ao16, g_ao16);
    cudaGetSymbolAddress((void**)&vt16, g_vt16);
    cudaGetSymbolAddress((void**)&w16q, g_w16q);
    cudaGetSymbolAddress((void**)&w16k, g_w16k);
    cudaGetSymbolAddress((void**)&w16v, g_w16v);
    cudaGetSymbolAddress((void**)&w16o, g_w16o);

    cudaFuncSetAttribute(gemm_mma, cudaFuncAttributeMaxDynamicSharedMemorySize, G_SMEM);
    cudaFuncSetAttribute(flash_mma, cudaFuncAttributeMaxDynamicSharedMemorySize, F_SMEM);

    // prep
    convert_x_kernel<<<S_TOT * DIM / 4 / 256, 256>>>(x, x16);
    WPtrs wp;
    wp.w[0] = Wq; wp.t16[0] = w16q;
    wp.w[1] = Wk; wp.t16[1] = w16k;
    wp.w[2] = Wv; wp.t16[2] = w16v;
    wp.w[3] = Wo; wp.t16[3] = w16o;
    transw_kernel<<<dim3(48, 48, 4), dim3(32, 8)>>>(wp);

    // fused QKV projection; V written directly as transposed fp16
    QKVArgs aqkv;
    aqkv.b16[0] = w16q; aqkv.bias[0] = bq; aqkv.c[0] = q;
    aqkv.b16[1] = w16k; aqkv.bias[1] = bk; aqkv.c[1] = k;
    aqkv.b16[2] = w16v; aqkv.bias[2] = bv; aqkv.c[2] = nullptr;
    aqkv.vt16 = vt16;
    gemm_mma<<<dim3(36, 31), 256, G_SMEM>>>(x16, aqkv, S_TOT, 0);

    rmsnorm_rope_conv<<<dim3(S_TOT, 2), 256>>>(q, gq, q16, k, gk, k16, freqs, grid_sz);

    // 3-way split-KV flash: partials into g_q, g_k, g_o2 (all free now)
    dim3 fg(31, NH, NSPLIT);
    flash_mma<<<fg, 256, F_SMEM>>>(q16, k16, vt16, q, k, o2, stat, seq_lens);
    combine_kernel<<<dim3(S_TOT, NH), 128>>>(q, k, o2, stat, ao16);

    // O projection: split-K=3 into fp32 partials, then add+bias
    QKVArgs aop;
    aop.b16[0] = w16o; aop.bias[0] = nullptr; aop.c[0] = q;
    aop.b16[1] = w16o; aop.bias[1] = nullptr; aop.c[1] = k;
    aop.b16[2] = w16o; aop.bias[2] = nullptr; aop.c[2] = o2;
    aop.vt16 = nullptr;
    gemm_mma<<<dim3(12, 31, 3), 256, G_SMEM>>>(ao16, aop, S_TOT, 1);
    addbias_kernel<<<S_TOT * DIM / 4 / 256, 256>>>(q, k, o2, bo, out);
}

// round 17
// speedup vs baseline: 1.0974x; 1.0974x over previous
#include <cuda_runtime.h>
#include <cuda_bf16.h>
#include <cuda_fp16.h>
#include <math.h>
#include <stdint.h>

#define S_TOT 3900
#define SP    3904        // padded seq (61*64)
#define DIM   1536
#define NH    12
#define HD    128
#define CC    64
#define NTILES 61         // SP/64
#define NSPLIT 3          // flash KV splits

// ---------------- scratch ----------------
__device__ float g_q [S_TOT * DIM];   // q fp32 -> flash partial 0 -> O-proj partial 0
__device__ float g_k [S_TOT * DIM];   // k fp32 -> flash partial 1 -> O-proj partial 1
__device__ float g_o2[S_TOT * DIM];   // flash partial 2 -> O-proj partial 2
__device__ float g_stat[NSPLIT * NH * 2 * 4096];

__device__ __half g_x16 [S_TOT * DIM];    // x fp16
__device__ __half g_q16 [S_TOT * DIM];    // Q fp16 (post rmsnorm+rope)
__device__ __half g_k16 [S_TOT * DIM];    // K fp16
__device__ __half g_ao16[S_TOT * DIM];    // attention out fp16
__device__ __half g_vt16[DIM * SP];       // V transposed fp16

__device__ __half g_w16q[DIM * DIM];
__device__ __half g_w16k[DIM * DIM];
__device__ __half g_w16v[DIM * DIM];
__device__ __half g_w16o[DIM * DIM];

// ================= helpers =================
__device__ __forceinline__ uint32_t smem_u32(const void* p) {
    uint32_t a;
    asm("{ .reg .u64 t; cvta.to.shared.u64 t, %1; cvt.u32.u64 %0, t; }" : "=r"(a) : "l"(p));
    return a;
}
__device__ __forceinline__ void ldsm4(uint32_t& r0, uint32_t& r1, uint32_t& r2, uint32_t& r3,
                                      uint32_t addr) {
    asm volatile("ldmatrix.sync.aligned.m8n8.x4.shared.b16 {%0,%1,%2,%3}, [%4];"
                 : "=r"(r0), "=r"(r1), "=r"(r2), "=r"(r3) : "r"(addr));
}
__device__ __forceinline__ void mma16816h(float* c, const uint32_t* a, const uint32_t* b) {
    asm volatile(
        "mma.sync.aligned.m16n8k16.row.col.f32.f16.f16.f32 "
        "{%0,%1,%2,%3}, {%4,%5,%6,%7}, {%8,%9}, {%0,%1,%2,%3};"
        : "+f"(c[0]), "+f"(c[1]), "+f"(c[2]), "+f"(c[3])
        : "r"(a[0]), "r"(a[1]), "r"(a[2]), "r"(a[3]), "r"(b[0]), "r"(b[1]));
}
#define CP16(dst, src, sz) \
    asm volatile("cp.async.cg.shared.global [%0], [%1], 16, %2;" \
        :: "r"(dst), "l"(src), "r"(sz) : "memory")
#define CP_COMMIT() asm volatile("cp.async.commit_group;" ::: "memory")
#define CP_WAIT0()  asm volatile("cp.async.wait_group 0;" ::: "memory")
#define CP_WAIT1()  asm volatile("cp.async.wait_group 1;" ::: "memory")

__device__ __forceinline__ uint32_t pack_h2(float x, float y) {
    __half2 t = __floats2half2_rn(x, y);
    return *(uint32_t*)&t;
}
#define STATIDX(sp, hh, ml, s) ((((sp) * NH + (hh)) * 2 + (ml)) * 4096 + (s))

// ================= prep kernels =================
__global__ __launch_bounds__(256)
void convert_x_kernel(const float* __restrict__ x, __half* __restrict__ x16) {
    int i = blockIdx.x * 256 + threadIdx.x;
    const int tot4 = S_TOT * DIM / 4;
    if (i >= tot4) return;
    float4 v = ((const float4*)x)[i];
    ((uint2*)x16)[i] = make_uint2(pack_h2(v.x, v.y), pack_h2(v.z, v.w));
}

// W[K][N] fp32 -> Wt[N][K] fp16 ; 4 weights in one launch (blockIdx.z)
struct WPtrs { const float* w[4]; __half* t16[4]; };

__global__ __launch_bounds__(256)
void transw_kernel(WPtrs p) {
    __shared__ float t[32][33];
    const float* W = p.w[blockIdx.z];
    __half* T = p.t16[blockIdx.z];
    const int n0 = blockIdx.x * 32, k0 = blockIdx.y * 32;
    const int tx = threadIdx.x, ty = threadIdx.y;
    #pragma unroll
    for (int i = 0; i < 4; i++)
        t[ty + i * 8][tx] = W[(size_t)(k0 + ty + i * 8) * DIM + n0 + tx];
    __syncthreads();
    #pragma unroll
    for (int i = 0; i < 4; i++) {
        float v = t[tx][ty + i * 8];
        T[(size_t)(n0 + ty + i * 8) * DIM + k0 + tx] = __float2half_rn(v);
    }
}

// RMSNorm + RoPE -> fp16 (y==0 Q, y==1 K)
__global__ __launch_bounds__(256)
void rmsnorm_rope_conv(const float* __restrict__ tq, const float* __restrict__ gq,
                       __half* __restrict__ qo16,
                       const float* __restrict__ tk, const float* __restrict__ gk,
                       __half* __restrict__ ko16,
                       const float* __restrict__ freqs, const int* __restrict__ grid_sizes) {
    const int s = blockIdx.x;
    const int tid = threadIdx.x;
    const int isq = (blockIdx.y == 0);
    const float* t  = isq ? tq : tk;
    const float* g  = isq ? gq : gk;
    __half* o16 = isq ? qo16 : ko16;
    const float* row = t + (size_t)s * DIM;

    float ss = 0.f;
    for (int i = tid; i < DIM / 4; i += 256) {
        float4 v = ((const float4*)row)[i];
        ss += v.x * v.x + v.y * v.y + v.z * v.z + v.w * v.w;
    }
    #pragma unroll
    for (int off = 16; off; off >>= 1) ss += __shfl_xor_sync(0xffffffffu, ss, off);
    __shared__ float red[8];
    if ((tid & 31) == 0) red[tid >> 5] = ss;
    __syncthreads();
    if (tid == 0) {
        float tot = 0.f;
        #pragma unroll
        for (int i = 0; i < 8; i++) tot += red[i];
        red[0] = tot;
    }
    __syncthreads();
    const float inv = rsqrtf(red[0] * (1.f / DIM) + 1e-6f);

    const int H = grid_sizes[1], W = grid_sizes[2];
    const int fi = s / (H * W);
    const int rem = s % (H * W);
    const int hi = rem / W;
    const int wi = rem % W;
    const int c3 = CC / 3, c0 = CC - 2 * c3;

    for (int p = tid; p < NH * CC; p += 256) {
        int j = p % CC;
        int head = p / CC;
        int idx = head * HD + 2 * j;
        float a = row[idx]     * inv * g[idx];
        float b = row[idx + 1] * inv * g[idx + 1];
        int pos = (j < c0) ? fi : ((j < c0 + c3) ? hi : wi);
        float cs = freqs[(pos * CC + j) * 2 + 0];
        float sn = freqs[(pos * CC + j) * 2 + 1];
        float ra = a * cs - b * sn;
        float rb = a * sn + b * cs;
        *(uint32_t*)(o16 + (size_t)s * DIM + idx) = pack_h2(ra, rb);
    }
}

// ================= HMMA GEMM: fp16 x fp16, single pass, 3-stage cp.async =========
#define G_ST   40
#define G_BUFB 10240
#define G_AS   0               // 3 bufs: 0..30720
#define G_BS   30720           // 3 bufs: 30720..61440
#define G_SMEM 61440           // V staging (34816) fits inside
#define VT_ST  136

struct QKVArgs {
    const __half* b16[3];
    const float* bias[3];
    float* c[3];
    __half* vt16;              // if non-null: mat==2 writes transposed fp16
};

__global__ __launch_bounds__(256)
void gemm_mma(const __half* __restrict__ A, QKVArgs args, int M, int splitk) {
    extern __shared__ char smc[];
    const uint32_t sb = smem_u32(smc);
    const int tid = threadIdx.x;
    const int lane = tid & 31;
    const int wid = tid >> 5;
    const int wm = wid & 1;
    const int wn = wid >> 1;
    int mat = blockIdx.x / 12;
    const int n0 = (blockIdx.x % 12) * 128;
    const int m0 = blockIdx.y * 128;
    int kt0 = 0, ktn = 48;
    if (splitk) { kt0 = blockIdx.z * 16; ktn = 16; mat = blockIdx.z; }
    const __half* B = args.b16[splitk ? 0 : mat];
    const float* bias = args.bias[mat];
    float* C = args.c[mat];

    float c[4][4][4];
    #pragma unroll
    for (int i = 0; i < 4; i++)
        #pragma unroll
        for (int j = 0; j < 4; j++)
            #pragma unroll
            for (int q = 0; q < 4; q++) c[i][j][q] = 0.f;

    auto stage = [&](int kt, int buf) {
        const int k0 = kt * 32;
        #pragma unroll
        for (int cix = 0; cix < 2; cix++) {
            int ch = tid + cix * 256;           // 0..511
            int row = ch >> 2, cc = (ch & 3) * 8;
            uint32_t so = (uint32_t)(row * G_ST + cc) * 2 + (uint32_t)buf * G_BUFB;
            int szA = (m0 + row < M) ? 16 : 0;
            const __half* pa = A + (size_t)(m0 + row) * DIM + k0 + cc;
            const __half* pb = B + (size_t)(n0 + row) * DIM + k0 + cc;
            CP16(sb + G_AS + so, pa, szA);
            CP16(sb + G_BS + so, pb, 16);
        }
        CP_COMMIT();
    };

    stage(kt0, 0);
    stage(kt0 + 1, 1);

    const int a_row = (lane & 15);
    const int a_col = ((lane >> 1) & 8);
    const int b_row = (lane & 7) + ((lane & 16) >> 1);
    const int b_col = (lane & 8);

    for (int kti = 0; kti < ktn; kti++) {
        CP_WAIT1();                      // stage kti complete (kti+1 may be in flight)
        __syncthreads();
        if (kti < ktn - 2) stage(kt0 + kti + 2, (kti + 2) % 3);
        const int bo = (kti % 3) * G_BUFB;
        #pragma unroll
        for (int kc = 0; kc < 32; kc += 16) {
            uint32_t af[4][4], bf[4][2];
            #pragma unroll
            for (int mt = 0; mt < 4; mt++)
                ldsm4(af[mt][0], af[mt][1], af[mt][2], af[mt][3],
                      sb + G_AS + bo + (uint32_t)((wm * 64 + mt * 16 + a_row) * G_ST + kc + a_col) * 2);
            #pragma unroll
            for (int np = 0; np < 2; np++) {
                uint32_t r0, r1, r2, r3;
                ldsm4(r0, r1, r2, r3,
                      sb + G_BS + bo + (uint32_t)((wn * 32 + np * 16 + b_row) * G_ST + kc + b_col) * 2);
                bf[np*2][0] = r0; bf[np*2][1] = r1; bf[np*2+1][0] = r2; bf[np*2+1][1] = r3;
            }
            #pragma unroll
            for (int mt = 0; mt < 4; mt++)
                #pragma unroll
                for (int nt = 0; nt < 4; nt++)
                    mma16816h(c[mt][nt], af[mt], bf[nt]);
        }
        __syncthreads();
    }
    CP_WAIT0();                          // drain the tail in-flight group

    if (args.vt16 != nullptr && mat == 2) {
        // ---- V epilogue: transposed fp16 via smem staging ----
        unsigned short* TH = (unsigned short*)smc;
        #pragma unroll
        for (int mt = 0; mt < 4; mt++) {
            #pragma unroll
            for (int nt = 0; nt < 4; nt++) {
                int row0 = wm * 64 + mt * 16 + (lane >> 2);
                int coll = wn * 32 + nt * 8 + (lane & 3) * 2;
                float b0 = bias[n0 + coll], b1 = bias[n0 + coll + 1];
                TH[coll * VT_ST + row0] =
                    __half_as_ushort(__float2half_rn(c[mt][nt][0] + b0));
                TH[(coll + 1) * VT_ST + row0] =
                    __half_as_ushort(__float2half_rn(c[mt][nt][1] + b1));
                TH[coll * VT_ST + row0 + 8] =
                    __half_as_ushort(__float2half_rn(c[mt][nt][2] + b0));
                TH[(coll + 1) * VT_ST + row0 + 8] =
                    __half_as_ushort(__float2half_rn(c[mt][nt][3] + b1));
            }
        }
        __syncthreads();
        #pragma unroll
        for (int it = 0; it < 8; it++) {
            int ch = tid + it * 256;         // 0..2047
            int drow = ch >> 4;
            int c8 = (ch & 15) * 8;
            if (m0 + c8 + 8 <= SP) {         // guard: last M-block overhangs SP
                uint4 v = *(uint4*)(smc + (uint32_t)(drow * VT_ST + c8) * 2);
                *(uint4*)(args.vt16 + (size_t)(n0 + drow) * SP + m0 + c8) = v;
            }
        }
    } else {
        #pragma unroll
        for (int mt = 0; mt < 4; mt++) {
            #pragma unroll
            for (int nt = 0; nt < 4; nt++) {
                int row = m0 + wm * 64 + mt * 16 + (lane >> 2);
                int col = n0 + wn * 32 + nt * 8 + (lane & 3) * 2;
                float b0 = 0.f, b1 = 0.f;
                if (!splitk) { b0 = bias[col]; b1 = bias[col + 1]; }
                if (row < M)
                    *(float2*)&C[(size_t)row * DIM + col] =
                        make_float2(c[mt][nt][0] + b0, c[mt][nt][1] + b1);
                if (row + 8 < M)
                    *(float2*)&C[(size_t)(row + 8) * DIM + col] =
                        make_float2(c[mt][nt][2] + b0, c[mt][nt][3] + b1);
            }
        }
    }
}

// ================= add split-K partials + bias (3-way) =================
__global__ __launch_bounds__(256)
void addbias_kernel(const float* __restrict__ p0, const float* __restrict__ p1,
                    const float* __restrict__ p2, const float* __restrict__ bias,
                    float* __restrict__ out) {
    int i = blockIdx.x * 256 + threadIdx.x;
    const int tot4 = S_TOT * DIM / 4;
    if (i >= tot4) return;
    float4 a = ((const float4*)p0)[i];
    float4 b = ((const float4*)p1)[i];
    float4 d = ((const float4*)p2)[i];
    float4 bb = ((const float4*)bias)[i % (DIM / 4)];
    ((float4*)out)[i] = make_float4(a.x + b.x + d.x + bb.x, a.y + b.y + d.y + bb.y,
                                    a.z + b.z + d.z + bb.z, a.w + b.w + d.w + bb.w);
}

// ================= HMMA flash attention: fp16, 2-buffer KV (R13 config) ==========
#define F_QST 136
#define F_VST 72
#define F_Q    0               // Q fp16: 128*136*2 = 34816
#define F_STG  34816
#define F_STGB 35840           // K 17408 | V 18432
#define F_SMEM (F_STG + 2 * F_STGB)   // 106496

__global__ __launch_bounds__(256)
void flash_mma(const __half* __restrict__ Q16, const __half* __restrict__ K16,
               const __half* __restrict__ V16,
               float* __restrict__ O0, float* __restrict__ O1, float* __restrict__ O2,
               float* __restrict__ stat, const int* __restrict__ seq_lens) {
    extern __shared__ char smc[];
    const uint32_t sb = smem_u32(smc);
    const int tid = threadIdx.x;
    const int lane = tid & 31;
    const int wid = tid >> 5;
    const int r0w = wid * 16;
    const int h = blockIdx.y;
    const int q0 = blockIdx.x * 128;
    const int sp = blockIdx.z;                      // 0,1,2
    const int t_begin = (sp == 0) ? 0 : 21 + (sp - 1) * 20;
    const int t_cnt   = (sp == 0) ? 21 : 20;
    const int seqlen = seq_lens[0];
    const float scale2 = 0.08838834764831845f * 1.4426950408889634f;  // /sqrt(128)*log2(e)

    // ---- Q tile [128 x 128] fp16 via cp.async ----
    #pragma unroll
    for (int cix = 0; cix < 8; cix++) {
        int ch = tid + cix * 256;                   // 0..2047
        int row = ch >> 4, cc = (ch & 15) * 8;
        int sz = (q0 + row < S_TOT) ? 16 : 0;
        const __half* gq = Q16 + (size_t)(q0 + row) * DIM + h * HD + cc;
        CP16(sb + F_Q + (uint32_t)(row * F_QST + cc) * 2, gq, sz);
    }
    CP_COMMIT();

    auto kv_stage = [&](int gt, int buf) {
        const int k0 = gt * 64;
        const uint32_t base = sb + F_STG + (uint32_t)buf * F_STGB;
        #pragma unroll
        for (int cix = 0; cix < 4; cix++) {
            int ch = tid + cix * 256;            // 0..1023
            {
                int row = ch >> 4, cc = (ch & 15) * 8;
                int sz = (k0 + row < S_TOT) ? 16 : 0;
                const __half* gk = K16 + (size_t)(k0 + row) * DIM + h * HD + cc;
                CP16(base + (uint32_t)(row * F_QST + cc) * 2, gk, sz);
            }
            {
                int row = ch >> 3, cc = (ch & 7) * 8;
                const __half* gv = V16 + (size_t)(h * HD + row) * SP + k0 + cc;
                CP16(base + 17408 + (uint32_t)(row * F_VST + cc) * 2, gv, 16);
            }
        }
        CP_COMMIT();
    };

    kv_stage(t_begin, 0);

    float m0s = -1e30f, m1s = -1e30f, l0s = 0.f, l1s = 0.f;
    float o[16][4];
    #pragma unroll
    for (int i = 0; i < 16; i++)
        #pragma unroll
        for (int j = 0; j < 4; j++) o[i][j] = 0.f;

    const int a_row = (lane & 15);
    const int a_col = ((lane >> 1) & 8);
    const int b_row = (lane & 7) + ((lane & 16) >> 1);
    const int b_col = (lane & 8);

    for (int lt = 0; lt < t_cnt; lt++) {
        const int gt = t_begin + lt;
        const int k0 = gt * 64;
        CP_WAIT0();
        __syncthreads();
        if (lt + 1 < t_cnt) kv_stage(gt + 1, (lt + 1) & 1);

        const uint32_t kb = sb + F_STG + (uint32_t)(lt & 1) * F_STGB;
        const uint32_t vb = kb + 17408;

        // ---- S = Q K^T (fp16, 1 pass) ----
        float c[8][4];
        #pragma unroll
        for (int nt = 0; nt < 8; nt++)
            #pragma unroll
            for (int j = 0; j < 4; j++) c[nt][j] = 0.f;

        #pragma unroll
        for (int kc8 = 0; kc8 < 8; kc8++) {
            const int kc = kc8 * 16;
            uint32_t aq[4], bk[8][2];
            ldsm4(aq[0], aq[1], aq[2], aq[3],
                  sb + F_Q + (uint32_t)((r0w + a_row) * F_QST + kc + a_col) * 2);
            #pragma unroll
            for (int np = 0; np < 4; np++) {
                uint32_t r0, r1, r2, r3;
                ldsm4(r0, r1, r2, r3,
                      kb + (uint32_t)((np * 16 + b_row) * F_QST + kc + b_col) * 2);
                bk[np*2][0] = r0; bk[np*2][1] = r1; bk[np*2+1][0] = r2; bk[np*2+1][1] = r3;
            }
            #pragma unroll
            for (int nt = 0; nt < 8; nt++)
                mma16816h(c[nt], aq, bk[nt]);
        }

        // ---- scale (log2 domain) + mask ----
        #pragma unroll
        for (int nt = 0; nt < 8; nt++) {
            int colb = k0 + nt * 8 + (lane & 3) * 2;
            #pragma unroll
            for (int j = 0; j < 4; j++) {
                float v = c[nt][j] * scale2;
                c[nt][j] = (colb + (j & 1) < seqlen) ? v : -1e30f;
            }
        }

        // ---- online softmax (exp2) ----
        float mx0 = -1e30f, mx1 = -1e30f;
        #pragma unroll
        for (int nt = 0; nt < 8; nt++) {
            mx0 = fmaxf(mx0, fmaxf(c[nt][0], c[nt][1]));
            mx1 = fmaxf(mx1, fmaxf(c[nt][2], c[nt][3]));
        }
        mx0 = fmaxf(mx0, __shfl_xor_sync(0xffffffffu, mx0, 1));
        mx0 = fmaxf(mx0, __shfl_xor_sync(0xffffffffu, mx0, 2));
        mx1 = fmaxf(mx1, __shfl_xor_sync(0xffffffffu, mx1, 1));
        mx1 = fmaxf(mx1, __shfl_xor_sync(0xffffffffu, mx1, 2));
        float mn0 = fmaxf(m0s, mx0), mn1 = fmaxf(m1s, mx1);
        float al0 = exp2f(m0s - mn0), al1 = exp2f(m1s - mn1);
        m0s = mn0; m1s = mn1;
        float ls0 = 0.f, ls1 = 0.f;
        #pragma unroll
        for (int nt = 0; nt < 8; nt++) {
            c[nt][0] = exp2f(c[nt][0] - mn0); ls0 += c[nt][0];
            c[nt][1] = exp2f(c[nt][1] - mn0); ls0 += c[nt][1];
            c[nt][2] = exp2f(c[nt][2] - mn1); ls1 += c[nt][2];
            c[nt][3] = exp2f(c[nt][3] - mn1); ls1 += c[nt][3];
        }
        ls0 += __shfl_xor_sync(0xffffffffu, ls0, 1);
        ls0 += __shfl_xor_sync(0xffffffffu, ls0, 2);
        ls1 += __shfl_xor_sync(0xffffffffu, ls1, 1);
        ls1 += __shfl_xor_sync(0xffffffffu, ls1, 2);
        l0s = l0s * al0 + ls0;
        l1s = l1s * al1 + ls1;

        // ---- pack P into fp16 A fragments ----
        uint32_t ph[4][4];
        #pragma unroll
        for (int kc2 = 0; kc2 < 4; kc2++) {
            ph[kc2][0] = pack_h2(c[2*kc2][0],   c[2*kc2][1]);
            ph[kc2][1] = pack_h2(c[2*kc2][2],   c[2*kc2][3]);
            ph[kc2][2] = pack_h2(c[2*kc2+1][0], c[2*kc2+1][1]);
            ph[kc2][3] = pack_h2(c[2*kc2+1][2], c[2*kc2+1][3]);
        }

        // ---- rescale O ----
        #pragma unroll
        for (int nt = 0; nt < 16; nt++) {
            o[nt][0] *= al0; o[nt][1] *= al0;
            o[nt][2] *= al1; o[nt][3] *= al1;
        }

        // ---- O += P V (fp16, 1 pass) ----
        #pragma unroll
        for (int kc2 = 0; kc2 < 4; kc2++) {
            #pragma unroll
            for (int np = 0; np < 8; np++) {
                uint32_t v0, v1, v2, v3;
                ldsm4(v0, v1, v2, v3,
                      vb + (uint32_t)((np * 16 + b_row) * F_VST + kc2 * 16 + b_col) * 2);
                uint32_t b0[2] = {v0, v1}, b1[2] = {v2, v3};
                mma16816h(o[2*np],   ph[kc2], b0);
                mma16816h(o[2*np+1], ph[kc2], b1);
            }
        }
    }

    // ---- write UNNORMALIZED partial + stats ----
    float* Op = (sp == 0) ? O0 : ((sp == 1) ? O1 : O2);
    const int rA = q0 + r0w + (lane >> 2);
    const int rB = rA + 8;
    #pragma unroll
    for (int nt = 0; nt < 16; nt++) {
        int col = h * HD + nt * 8 + (lane & 3) * 2;
        if (rA < S_TOT)
            *(float2*)&Op[(size_t)rA * DIM + col] = make_float2(o[nt][0], o[nt][1]);
        if (rB < S_TOT)
            *(float2*)&Op[(size_t)rB * DIM + col] = make_float2(o[nt][2], o[nt][3]);
    }
    if ((lane & 3) == 0) {
        if (rA < S_TOT) {
            stat[STATIDX(sp, h, 0, rA)] = m0s;
            stat[STATIDX(sp, h, 1, rA)] = l0s;
        }
        if (rB < S_TOT) {
            stat[STATIDX(sp, h, 0, rB)] = m1s;
            stat[STATIDX(sp, h, 1, rB)] = l1s;
        }
    }
}

// ================= combine split-KV partials (3-way, float4 vectorized) =========
__global__ __launch_bounds__(256)
void combine_kernel(const float* __restrict__ O0, const float* __restrict__ O1,
                    const float* __restrict__ O2, const float* __restrict__ stat,
                    __half* __restrict__ AO16) {
    int i = blockIdx.x * 256 + threadIdx.x;        // float4 index
    const int tot4 = S_TOT * DIM / 4;
    if (i >= tot4) return;
    int e = i * 4;
    int s = e / DIM;
    int col = e - s * DIM;
    int h = col >> 7;                              // col / HD
    float mA = stat[STATIDX(0, h, 0, s)], lA = stat[STATIDX(0, h, 1, s)];
    float mB = stat[STATIDX(1, h, 0, s)], lB = stat[STATIDX(1, h, 1, s)];
    float mC = stat[STATIDX(2, h, 0, s)], lC = stat[STATIDX(2, h, 1, s)];
    float m = fmaxf(fmaxf(mA, mB), mC);
    float aA = exp2f(mA - m), aB = exp2f(mB - m), aC = exp2f(mC - m);
    float inv = 1.f / (lA * aA + lB * aB + lC * aC);
    float4 a = ((const float4*)O0)[i];
    float4 b = ((const float4*)O1)[i];
    float4 d = ((const float4*)O2)[i];
    float r0 = (a.x * aA + b.x * aB + d.x * aC) * inv;
    float r1 = (a.y * aA + b.y * aB + d.y * aC) * inv;
    float r2 = (a.z * aA + b.z * aB + d.z * aC) * inv;
    float r3 = (a.w * aA + b.w * aB + d.w * aC) * inv;
    ((uint2*)AO16)[i] = make_uint2(pack_h2(r0, r1), pack_h2(r2, r3));
}

// ---------------- launch ----------------
extern "C" void kernel_launch(void* const* d_in, const int* in_sizes, int n_in,
                              void* d_out, int out_size) {
    const float* x        = (const float*)d_in[0];
    const int*   seq_lens = (const int*)  d_in[1];
    const int*   grid_sz  = (const int*)  d_in[2];
    const float* freqs    = (const float*)d_in[3];
    const float* Wq       = (const float*)d_in[4];
    const float* bq       = (const float*)d_in[5];
    const float* Wk       = (const float*)d_in[6];
    const float* bk       = (const float*)d_in[7];
    const float* Wv       = (const float*)d_in[8];
    const float* bv       = (const float*)d_in[9];
    const float* Wo       = (const float*)d_in[10];
    const float* bo       = (const float*)d_in[11];
    const float* gq       = (const float*)d_in[12];
    const float* gk       = (const float*)d_in[13];
    float* out = (float*)d_out;

    float *q, *k, *o2, *stat;
    __half *x16, *q16, *k16, *ao16, *vt16;
    __half *w16q, *w16k, *w16v, *w16o;
    cudaGetSymbolAddress((void**)&q, g_q);
    cudaGetSymbolAddress((void**)&k, g_k);
    cudaGetSymbolAddress((void**)&o2, g_o2);
    cudaGetSymbolAddress((void**)&stat, g_stat);
    cudaGetSymbolAddress((void**)&x16, g_x16);
    cudaGetSymbolAddress((void**)&q16, g_q16);
    cudaGetSymbolAddress((void**)&k16, g_k16);
    cudaGetSymbolAddress((void**)&ao16, g_ao16);
    cudaGetSymbolAddress((void**)&vt16, g_vt16);
    cudaGetSymbolAddress((void**)&w16q, g_w16q);
    cudaGetSymbolAddress((void**)&w16k, g_w16k);
    cudaGetSymbolAddress((void**)&w16v, g_w16v);
    cudaGetSymbolAddress((void**)&w16o, g_w16o);

    cudaFuncSetAttribute(gemm_mma, cudaFuncAttributeMaxDynamicSharedMemorySize, G_SMEM);
    cudaFuncSetAttribute(flash_mma, cudaFuncAttributeMaxDynamicSharedMemorySize, F_SMEM);

    // prep
    convert_x_kernel<<<S_TOT * DIM / 4 / 256, 256>>>(x, x16);
    WPtrs wp;
    wp.w[0] = Wq; wp.t16[0] = w16q;
    wp.w[1] = Wk; wp.t16[1] = w16k;
    wp.w[2] = Wv; wp.t16[2] = w16v;
    wp.w[3] = Wo; wp.t16[3] = w16o;
    transw_kernel<<<dim3(48, 48, 4), dim3(32, 8)>>>(wp);

    // fused QKV projection; V written directly as transposed fp16
    QKVArgs aqkv;
    aqkv.b16[0] = w16q; aqkv.bias[0] = bq; aqkv.c[0] = q;
    aqkv.b16[1] = w16k; aqkv.bias[1] = bk; aqkv.c[1] = k;
    aqkv.b16[2] = w16v; aqkv.bias[2] = bv; aqkv.c[2] = nullptr;
    aqkv.vt16 = vt16;
    gemm_mma<<<dim3(36, 31), 256, G_SMEM>>>(x16, aqkv, S_TOT, 0);

    rmsnorm_rope_conv<<<dim3(S_TOT, 2), 256>>>(q, gq, q16, k, gk, k16, freqs, grid_sz);

    // 3-way split-KV flash: partials into g_q, g_k, g_o2 (all free now)
    dim3 fg(31, NH, NSPLIT);
    flash_mma<<<fg, 256, F_SMEM>>>(q16, k16, vt16, q, k, o2, stat, seq_lens);
    combine_kernel<<<(S_TOT * DIM / 4 + 255) / 256, 256>>>(q, k, o2, stat, ao16);

    // O projection: split-K=3 into fp32 partials, then add+bias
    QKVArgs aop;
    aop.b16[0] = w16o; aop.bias[0] = nullptr; aop.c[0] = q;
    aop.b16[1] = w16o; aop.bias[1] = nullptr; aop.c[1] = k;
    aop.b16[2] = w16o; aop.bias[2] = nullptr; aop.c[2] = o2;
    aop.vt16 = nullptr;
    gemm_mma<<<dim3(12, 31, 3), 256, G_SMEM>>>(ao16, aop, S_TOT, 1);
    addbias_kernel<<<S_TOT * DIM / 4 / 256, 256>>>(q, k, o2, bo, out);
}